// round 2
// baseline (speedup 1.0000x reference)
#include <cuda_runtime.h>

#define EDGES   65536
#define NODESN  2048
#define DI      64
#define DOUT    64
#define EPSV    1e-6f

// scratch (no cudaMalloc allowed)
__device__ int   g_si[EDGES];     // src index per edge
__device__ int   g_ti[EDGES];     // tgt index per edge
__device__ float g_aexp[EDGES];   // exp(a)   (mean shift algebraically cancels)
__device__ float g_asum[NODESN];  // per-target-node softmax denominator

// ---------------------------------------------------------------------------
// K0: zero output + denominators
// ---------------------------------------------------------------------------
__global__ void k_zero(float* __restrict__ out) {
    int i = blockIdx.x * blockDim.x + threadIdx.x;
    if (i < NODESN * DOUT) out[i] = 0.0f;
    if (i < NODESN) g_asum[i] = 0.0f;
}

// ---------------------------------------------------------------------------
// K1 (fused): one-hot index scan + attention logit + exp + denominator.
// One thread per edge; scans all 2048 rows of src & tgt for its column
// (coalesced 128B/warp, streaming .cs to bypass L2 for the 1 GB read),
// then gathers x[s], x[t] (L2-hot) and dots with smem-cached W_w.
// No mean subtraction: softmax ratio is shift-invariant up to EPS*e^m (~2e-8).
// ---------------------------------------------------------------------------
__global__ void __launch_bounds__(256) k_fused(const float* __restrict__ src,
                                               const float* __restrict__ tgt,
                                               const float* __restrict__ x,
                                               const float* __restrict__ Ww,
                                               const float* __restrict__ bw) {
    __shared__ float sWw[2 * DI];
    if (threadIdx.x < 2 * DI) sWw[threadIdx.x] = Ww[threadIdx.x];
    __syncthreads();

    const int e = blockIdx.x * blockDim.x + threadIdx.x;
    const float* ps = src + e;
    const float* pt = tgt + e;

    float fs = 0.0f, ft = 0.0f;
    float fn = 0.0f;
#pragma unroll 8
    for (int n = 0; n < NODESN; ++n) {
        float vs = __ldcs(ps + (size_t)n * EDGES);
        float vt = __ldcs(pt + (size_t)n * EDGES);
        fs += vs * fn;
        ft += vt * fn;
        fn += 1.0f;
    }
    const int s = (int)(fs + 0.5f);
    const int t = (int)(ft + 0.5f);
    g_si[e] = s;
    g_ti[e] = t;

    // attention logit a = [x[s], x[t]] . W_w + b_w
    const float4* xs = (const float4*)(x + s * DI);
    const float4* xt = (const float4*)(x + t * DI);
    const float4* w0 = (const float4*)sWw;
    const float4* w1 = (const float4*)(sWw + DI);

    float acc = bw[0];
#pragma unroll
    for (int k = 0; k < DI / 4; ++k) {
        float4 a = xs[k], b = w0[k];
        acc += a.x * b.x + a.y * b.y + a.z * b.z + a.w * b.w;
        float4 c = xt[k], d = w1[k];
        acc += c.x * d.x + c.y * d.y + c.z * d.z + c.w * d.w;
    }
    float ae = expf(acc);
    g_aexp[e] = ae;
    atomicAdd(&g_asum[t], ae);
}

// ---------------------------------------------------------------------------
// K2: fused Y = relu(H @ W_f + b_f), weight by edge softmax, scatter to out.
// Block = 256 threads handles 64 edges; hT[k][e] staged transposed in smem.
// Each thread: 4 edges x 4 dims register tile (16 FFMA per LDS/LDG pair).
// ---------------------------------------------------------------------------
#define BE 64
__global__ void __launch_bounds__(256) k_out(const float* __restrict__ x,
                                             const float* __restrict__ Wf,
                                             const float* __restrict__ bf,
                                             float* __restrict__ out) {
    __shared__ float hT[2 * DI * BE];   // hT[k*64 + e], k in [0,128)
    __shared__ float we[BE];
    __shared__ int   tg[BE];

    const int tid = threadIdx.x;
    const int e0 = blockIdx.x * BE;

    // per-edge meta
    if (tid < BE) {
        int e = e0 + tid;
        int t = g_ti[e];
        tg[tid] = t;
        we[tid] = g_aexp[e] / (g_asum[t] + EPSV);
    }

    // stage hT: thread (e = tid%64, q = tid/64) loads a 32-wide slice of x row
    {
        int e = tid & 63;
        int q = tid >> 6;                 // 0,1: src halves; 2,3: tgt halves
        int ge = e0 + e;
        int node = (q < 2) ? g_si[ge] : g_ti[ge];
        int kbase = (q & 1) * 32;         // element offset within x row
        int krow  = (q < 2) ? 0 : DI;     // offset in concatenated h
        const float4* xr = (const float4*)(x + node * DI + kbase);
#pragma unroll
        for (int i = 0; i < 8; ++i) {
            float4 v = xr[i];
            int k = krow + kbase + i * 4;
            hT[(k + 0) * BE + e] = v.x;
            hT[(k + 1) * BE + e] = v.y;
            hT[(k + 2) * BE + e] = v.z;
            hT[(k + 3) * BE + e] = v.w;
        }
    }
    __syncthreads();

    const int eg = tid & 15;   // edges eg*4 .. eg*4+3
    const int dg = tid >> 4;   // dims  dg*4 .. dg*4+3

    float acc[4][4] = {};
    const float4* Wf4 = (const float4*)Wf;
#pragma unroll 8
    for (int k = 0; k < 2 * DI; ++k) {
        float4 hv = *(const float4*)&hT[k * BE + eg * 4];
        float4 wv = __ldg(&Wf4[(k * DOUT + dg * 4) >> 2]);
        acc[0][0] += hv.x * wv.x; acc[0][1] += hv.x * wv.y; acc[0][2] += hv.x * wv.z; acc[0][3] += hv.x * wv.w;
        acc[1][0] += hv.y * wv.x; acc[1][1] += hv.y * wv.y; acc[1][2] += hv.y * wv.z; acc[1][3] += hv.y * wv.w;
        acc[2][0] += hv.z * wv.x; acc[2][1] += hv.z * wv.y; acc[2][2] += hv.z * wv.z; acc[2][3] += hv.z * wv.w;
        acc[3][0] += hv.w * wv.x; acc[3][1] += hv.w * wv.y; acc[3][2] += hv.w * wv.z; acc[3][3] += hv.w * wv.w;
    }

    float4 bv = __ldg((const float4*)&bf[dg * 4]);
#pragma unroll
    for (int i = 0; i < 4; ++i) {
        int el = eg * 4 + i;
        float w = we[el];
        int t = tg[el];
        float* op = out + t * DOUT + dg * 4;
        float y0 = fmaxf(acc[i][0] + bv.x, 0.0f) * w;
        float y1 = fmaxf(acc[i][1] + bv.y, 0.0f) * w;
        float y2 = fmaxf(acc[i][2] + bv.z, 0.0f) * w;
        float y3 = fmaxf(acc[i][3] + bv.w, 0.0f) * w;
        atomicAdd(&op[0], y0);
        atomicAdd(&op[1], y1);
        atomicAdd(&op[2], y2);
        atomicAdd(&op[3], y3);
    }
}

// ---------------------------------------------------------------------------
extern "C" void kernel_launch(void* const* d_in, const int* in_sizes, int n_in,
                              void* d_out, int out_size) {
    const float* x   = (const float*)d_in[0];
    const float* src = (const float*)d_in[1];
    const float* tgt = (const float*)d_in[2];
    const float* Wf  = (const float*)d_in[3];
    const float* bf  = (const float*)d_in[4];
    const float* Ww  = (const float*)d_in[5];
    const float* bw  = (const float*)d_in[6];
    float* out = (float*)d_out;

    k_zero<<<(NODESN * DOUT + 255) / 256, 256>>>(out);
    k_fused<<<EDGES / 256, 256>>>(src, tgt, x, Ww, bw);
    k_out<<<EDGES / BE, 256>>>(x, Wf, bf, out);
}

// round 3
// speedup vs baseline: 1.2446x; 1.2446x over previous
#include <cuda_runtime.h>

#define EDGES   65536
#define NODESN  2048
#define DI      64
#define DOUT    64
#define EPSV    1e-6f
#define RCHUNK  128            // rows per scan block

// scratch (no cudaMalloc allowed)
__device__ int   g_si[EDGES];     // src index per edge
__device__ int   g_ti[EDGES];     // tgt index per edge
__device__ float g_aexp[EDGES];   // exp(a)  (mean shift algebraically cancels)
__device__ float g_asum[NODESN];  // per-target-node softmax denominator

// ---------------------------------------------------------------------------
// K0: zero output + denominators (index arrays need no zeroing: exactly one
// chunk per edge writes them unconditionally-once in k_scan)
// ---------------------------------------------------------------------------
__global__ void k_zero(float* __restrict__ out) {
    int i = blockIdx.x * blockDim.x + threadIdx.x;
    if (i < NODESN * DOUT) out[i] = 0.0f;
    if (i < NODESN) g_asum[i] = 0.0f;
}

// ---------------------------------------------------------------------------
// K1: one-hot -> index extraction. Reads the full 1 GB (src + tgt) as float4.
// Each thread owns 4 edges (one float4 column group) within a 128-row chunk.
// Accumulates  widx = sum n*v  and presence  p = sum v.  Exactly one chunk
// has p==1 per edge -> that chunk alone stores the final int index (no atomics).
// grid: (E/4/256 = 64, N/RCHUNK = 16) x 256 threads = 1024 blocks.
// ---------------------------------------------------------------------------
__global__ void __launch_bounds__(256) k_scan(const float4* __restrict__ src4,
                                              const float4* __restrict__ tgt4) {
    const int g4 = blockIdx.x * blockDim.x + threadIdx.x;   // float4 group id
    const int r0 = blockIdx.y * RCHUNK;                     // row chunk start
    const int stride4 = EDGES / 4;                          // 16384
    size_t base = (size_t)r0 * stride4 + g4;

    float4 ws = {0.f, 0.f, 0.f, 0.f}, wt = {0.f, 0.f, 0.f, 0.f};  // sum n*v
    float4 ps = {0.f, 0.f, 0.f, 0.f}, pt = {0.f, 0.f, 0.f, 0.f};  // sum v

#pragma unroll 8
    for (int n = 0; n < RCHUNK; ++n) {
        float fn = (float)(r0 + n);
        float4 vs = __ldcs(&src4[base]);
        float4 vt = __ldcs(&tgt4[base]);
        base += stride4;
        ws.x += vs.x * fn; ws.y += vs.y * fn; ws.z += vs.z * fn; ws.w += vs.w * fn;
        ps.x += vs.x;      ps.y += vs.y;      ps.z += vs.z;      ps.w += vs.w;
        wt.x += vt.x * fn; wt.y += vt.y * fn; wt.z += vt.z * fn; wt.w += vt.w * fn;
        pt.x += vt.x;      pt.y += vt.y;      pt.z += vt.z;      pt.w += vt.w;
    }
    int e0 = g4 * 4;
    if (ps.x > 0.5f) g_si[e0 + 0] = (int)(ws.x + 0.5f);
    if (ps.y > 0.5f) g_si[e0 + 1] = (int)(ws.y + 0.5f);
    if (ps.z > 0.5f) g_si[e0 + 2] = (int)(ws.z + 0.5f);
    if (ps.w > 0.5f) g_si[e0 + 3] = (int)(ws.w + 0.5f);
    if (pt.x > 0.5f) g_ti[e0 + 0] = (int)(wt.x + 0.5f);
    if (pt.y > 0.5f) g_ti[e0 + 1] = (int)(wt.y + 0.5f);
    if (pt.z > 0.5f) g_ti[e0 + 2] = (int)(wt.z + 0.5f);
    if (pt.w > 0.5f) g_ti[e0 + 3] = (int)(wt.w + 0.5f);
}

// ---------------------------------------------------------------------------
// K2: attention logit a = [x[s],x[t]].W_w + b_w, exp, per-target denominator.
// No mean subtraction (softmax shift-invariant; EPS perturbation ~2e-8 rel).
// ---------------------------------------------------------------------------
__global__ void __launch_bounds__(256) k_attn(const float* __restrict__ x,
                                              const float* __restrict__ Ww,
                                              const float* __restrict__ bw) {
    __shared__ float sWw[2 * DI];
    if (threadIdx.x < 2 * DI) sWw[threadIdx.x] = Ww[threadIdx.x];
    __syncthreads();

    int e = blockIdx.x * blockDim.x + threadIdx.x;
    int s = g_si[e];
    int t = g_ti[e];

    const float4* xs = (const float4*)(x + s * DI);
    const float4* xt = (const float4*)(x + t * DI);
    const float4* w0 = (const float4*)sWw;
    const float4* w1 = (const float4*)(sWw + DI);

    float acc = bw[0];
#pragma unroll
    for (int k = 0; k < DI / 4; ++k) {
        float4 a = xs[k], b = w0[k];
        acc += a.x * b.x + a.y * b.y + a.z * b.z + a.w * b.w;
        float4 c = xt[k], d = w1[k];
        acc += c.x * d.x + c.y * d.y + c.z * d.z + c.w * d.w;
    }
    float ae = expf(acc);
    g_aexp[e] = ae;
    atomicAdd(&g_asum[t], ae);
}

// ---------------------------------------------------------------------------
// K3: fused Y = relu(H @ W_f + b_f), weight by edge softmax, scatter to out.
// Block = 256 threads handles 64 edges; hT[k][e] staged transposed in smem.
// Each thread: 4 edges x 4 dims register tile (16 FFMA per LDS/LDG pair).
// ---------------------------------------------------------------------------
#define BE 64
__global__ void __launch_bounds__(256) k_out(const float* __restrict__ x,
                                             const float* __restrict__ Wf,
                                             const float* __restrict__ bf,
                                             float* __restrict__ out) {
    __shared__ float hT[2 * DI * BE];   // hT[k*64 + e], k in [0,128)
    __shared__ float we[BE];
    __shared__ int   tg[BE];

    const int tid = threadIdx.x;
    const int e0 = blockIdx.x * BE;

    if (tid < BE) {
        int e = e0 + tid;
        int t = g_ti[e];
        tg[tid] = t;
        we[tid] = g_aexp[e] / (g_asum[t] + EPSV);
    }

    // stage hT: thread (e = tid%64, q = tid/64) loads a 32-wide slice of x row
    {
        int e = tid & 63;
        int q = tid >> 6;                 // 0,1: src halves; 2,3: tgt halves
        int ge = e0 + e;
        int node = (q < 2) ? g_si[ge] : g_ti[ge];
        int kbase = (q & 1) * 32;
        int krow  = (q < 2) ? 0 : DI;
        const float4* xr = (const float4*)(x + node * DI + kbase);
#pragma unroll
        for (int i = 0; i < 8; ++i) {
            float4 v = xr[i];
            int k = krow + kbase + i * 4;
            hT[(k + 0) * BE + e] = v.x;
            hT[(k + 1) * BE + e] = v.y;
            hT[(k + 2) * BE + e] = v.z;
            hT[(k + 3) * BE + e] = v.w;
        }
    }
    __syncthreads();

    const int eg = tid & 15;   // edges eg*4 .. eg*4+3
    const int dg = tid >> 4;   // dims  dg*4 .. dg*4+3

    float acc[4][4] = {};
    const float4* Wf4 = (const float4*)Wf;
#pragma unroll 8
    for (int k = 0; k < 2 * DI; ++k) {
        float4 hv = *(const float4*)&hT[k * BE + eg * 4];
        float4 wv = __ldg(&Wf4[(k * DOUT + dg * 4) >> 2]);
        acc[0][0] += hv.x * wv.x; acc[0][1] += hv.x * wv.y; acc[0][2] += hv.x * wv.z; acc[0][3] += hv.x * wv.w;
        acc[1][0] += hv.y * wv.x; acc[1][1] += hv.y * wv.y; acc[1][2] += hv.y * wv.z; acc[1][3] += hv.y * wv.w;
        acc[2][0] += hv.z * wv.x; acc[2][1] += hv.z * wv.y; acc[2][2] += hv.z * wv.z; acc[2][3] += hv.z * wv.w;
        acc[3][0] += hv.w * wv.x; acc[3][1] += hv.w * wv.y; acc[3][2] += hv.w * wv.z; acc[3][3] += hv.w * wv.w;
    }

    float4 bv = __ldg((const float4*)&bf[dg * 4]);
#pragma unroll
    for (int i = 0; i < 4; ++i) {
        int el = eg * 4 + i;
        float w = we[el];
        int t = tg[el];
        float* op = out + t * DOUT + dg * 4;
        atomicAdd(&op[0], fmaxf(acc[i][0] + bv.x, 0.0f) * w);
        atomicAdd(&op[1], fmaxf(acc[i][1] + bv.y, 0.0f) * w);
        atomicAdd(&op[2], fmaxf(acc[i][2] + bv.z, 0.0f) * w);
        atomicAdd(&op[3], fmaxf(acc[i][3] + bv.w, 0.0f) * w);
    }
}

// ---------------------------------------------------------------------------
extern "C" void kernel_launch(void* const* d_in, const int* in_sizes, int n_in,
                              void* d_out, int out_size) {
    const float* x   = (const float*)d_in[0];
    const float* src = (const float*)d_in[1];
    const float* tgt = (const float*)d_in[2];
    const float* Wf  = (const float*)d_in[3];
    const float* bf  = (const float*)d_in[4];
    const float* Ww  = (const float*)d_in[5];
    const float* bw  = (const float*)d_in[6];
    float* out = (float*)d_out;

    k_zero<<<(NODESN * DOUT + 255) / 256, 256>>>(out);
    k_scan<<<dim3(EDGES / 4 / 256, NODESN / RCHUNK), 256>>>(
        (const float4*)src, (const float4*)tgt);
    k_attn<<<EDGES / 256, 256>>>(x, Ww, bw);
    k_out<<<EDGES / BE, 256>>>(x, Wf, bf, out);
}